// round 14
// baseline (speedup 1.0000x reference)
#include <cuda_runtime.h>

// ---------------------------------------------------------------------------
// Problem constants
// ---------------------------------------------------------------------------
#define S0    2048
#define S1    256
#define SEQ   2304          // S0 + S1
#define DIM   1536          // model dim == H*D
#define NH    24
#define HD    64
#define QKV_N 4608          // 3 * NH * HD

// ---------------------------------------------------------------------------
// Scratch
// ---------------------------------------------------------------------------
#define OFF_QKV0 0u
#define OFF_QKV1 9437184u
#define OFF_Q    10616832u
#define OFF_K    14155776u
#define OFF_V    17694720u
#define OFF_O    21233664u
#define SCRATCH_FLOATS 24772608u

__device__ float g_scratch[SCRATCH_FLOATS];

// ---------------------------------------------------------------------------
// SGEMM: C[M,N] = A[M,K] @ B[K,N], row-major fp32.
// BM=BN=128, BK=8, 256 threads, 8x8 microtile, double-buffered smem.
// ---------------------------------------------------------------------------
__global__ void __launch_bounds__(256) sgemm128(
    const float* __restrict__ A, const float* __restrict__ B,
    float* __restrict__ C, int N, int K)
{
    __shared__ float As[2][8][128];   // transposed A tile
    __shared__ float Bs[2][8][128];

    const int tid = threadIdx.x;
    const int tx = tid & 15;
    const int ty = tid >> 4;

    const float* Ab = A + (size_t)blockIdx.y * 128 * K;
    const float* Bb = B + (size_t)blockIdx.x * 128;

    const int aRow = tid >> 1;
    const int aCol = (tid & 1) * 4;
    const int bRow = tid >> 5;
    const int bCol = (tid & 31) * 4;

    float acc[8][8];
    #pragma unroll
    for (int i = 0; i < 8; i++)
        #pragma unroll
        for (int j = 0; j < 8; j++) acc[i][j] = 0.f;

    {
        float4 av = *(const float4*)(Ab + (size_t)aRow * K + aCol);
        As[0][aCol + 0][aRow] = av.x;
        As[0][aCol + 1][aRow] = av.y;
        As[0][aCol + 2][aRow] = av.z;
        As[0][aCol + 3][aRow] = av.w;
        float4 bv = *(const float4*)(Bb + (size_t)bRow * N + bCol);
        *(float4*)(&Bs[0][bRow][bCol]) = bv;
    }
    __syncthreads();

    int cur = 0;
    for (int k0 = 0; k0 < K; k0 += 8) {
        const bool has_next = (k0 + 8 < K);
        float4 av, bv;
        if (has_next) {
            av = *(const float4*)(Ab + (size_t)aRow * K + (k0 + 8) + aCol);
            bv = *(const float4*)(Bb + (size_t)(k0 + 8 + bRow) * N + bCol);
        }

        #pragma unroll
        for (int k = 0; k < 8; k++) {
            float ar[8], br[8];
            #pragma unroll
            for (int i = 0; i < 8; i++) ar[i] = As[cur][k][ty * 8 + i];
            #pragma unroll
            for (int j = 0; j < 8; j++) br[j] = Bs[cur][k][tx * 8 + j];
            #pragma unroll
            for (int i = 0; i < 8; i++)
                #pragma unroll
                for (int j = 0; j < 8; j++)
                    acc[i][j] = fmaf(ar[i], br[j], acc[i][j]);
        }

        if (has_next) {
            As[cur ^ 1][aCol + 0][aRow] = av.x;
            As[cur ^ 1][aCol + 1][aRow] = av.y;
            As[cur ^ 1][aCol + 2][aRow] = av.z;
            As[cur ^ 1][aCol + 3][aRow] = av.w;
            *(float4*)(&Bs[cur ^ 1][bRow][bCol]) = bv;
        }
        __syncthreads();
        cur ^= 1;
    }

    #pragma unroll
    for (int i = 0; i < 8; i++) {
        float* Crow = C + (size_t)(blockIdx.y * 128 + ty * 8 + i) * N
                        + blockIdx.x * 128 + tx * 8;
        *(float4*)(Crow)     = make_float4(acc[i][0], acc[i][1], acc[i][2], acc[i][3]);
        *(float4*)(Crow + 4) = make_float4(acc[i][4], acc[i][5], acc[i][6], acc[i][7]);
    }
}

// ---------------------------------------------------------------------------
// RMSNorm + RoPE + scatter to (H, SEQ, HD) Q/K/V. One warp per (s, head).
// ---------------------------------------------------------------------------
__global__ void norm_rope_kernel(
    const float* __restrict__ gq0, const float* __restrict__ gk0,
    const float* __restrict__ gq1, const float* __restrict__ gk1)
{
    const int s = blockIdx.x;
    const int h = blockIdx.y;
    const int d = threadIdx.x;     // 0..31

    const float* src;
    const float *gq, *gk;
    int pos;
    if (s < S0) {
        pos = s;
        src = g_scratch + OFF_QKV0 + (size_t)s * QKV_N;
        gq = gq0; gk = gk0;
    } else {
        pos = s - S0;
        src = g_scratch + OFF_QKV1 + (size_t)pos * QKV_N;
        gq = gq1; gk = gk1;
    }

    const int col = h * HD + d;
    float qa = src[col],            qb = src[col + 32];
    float ka = src[DIM + col],      kb = src[DIM + col + 32];
    float va = src[2 * DIM + col],  vb = src[2 * DIM + col + 32];

    float ssq = qa * qa + qb * qb;
    float ssk = ka * ka + kb * kb;
    #pragma unroll
    for (int o = 16; o; o >>= 1) {
        ssq += __shfl_xor_sync(0xffffffffu, ssq, o);
        ssk += __shfl_xor_sync(0xffffffffu, ssk, o);
    }
    float rq = rsqrtf(ssq * (1.f / 64.f) + 1e-6f);
    float rk = rsqrtf(ssk * (1.f / 64.f) + 1e-6f);
    qa *= rq * gq[d]; qb *= rq * gq[d + 32];
    ka *= rk * gk[d]; kb *= rk * gk[d + 32];

    float inv = powf(10000.f, -(float)(2 * d) * (1.f / 64.f));
    float f = (float)pos * inv;
    float sn, cs;
    sincosf(f, &sn, &cs);
    float qoa = qa * cs - qb * sn, qob = qb * cs + qa * sn;
    float koa = ka * cs - kb * sn, kob = kb * cs + ka * sn;

    const size_t base = ((size_t)h * SEQ + s) * HD;
    g_scratch[OFF_Q + base + d]      = qoa;
    g_scratch[OFF_Q + base + d + 32] = qob;
    g_scratch[OFF_K + base + d]      = koa;
    g_scratch[OFF_K + base + d + 32] = kob;
    g_scratch[OFF_V + base + d]      = va;
    g_scratch[OFF_V + base + d + 32] = vb;
}

// ---------------------------------------------------------------------------
// Flash attention v3: register-blocked (GEMM-style outer products).
// Block = (96-row q-tile, head), 128 threads.
// Thread (ty,tx) with ty=t>>3 (0..15), tx=t&7 (0..7) owns a 6x8 microtile:
//   q-rows  i = ty*6 + 0..5
//   k-cols  j = tx*8 + 0..7  (QK phase) / dims d = tx*8 + 0..7 (PV phase)
// Q,K in smem d-major (transposed); P transposed [k][row]; V natural [k][d].
// Per d/k step: 6 broadcast scalars + 2 float4 -> 48 FMAs (ratio 3.4).
// Softmax row stats via shfl over the 8-thread tx group (lane bits 0..2).
// Smem: Qs 64x97, Ks 64x68, Vs 64x68, Ps 64x97 = 84480 B (dynamic).
// ---------------------------------------------------------------------------
#define FL_QT   96
#define FL_SQ   97          // Qs/Ps row stride
#define FL_SK   68          // Ks/Vs row stride (float4-aligned)
#define FL_QS_OFF 0
#define FL_KS_OFF (64 * FL_SQ)                 // 6208
#define FL_VS_OFF (FL_KS_OFF + 64 * FL_SK)     // 10560
#define FL_PS_OFF (FL_VS_OFF + 64 * FL_SK)     // 14912
#define FL_SMEM_FLOATS (FL_PS_OFF + 64 * FL_SQ)  // 21120
#define FL_SMEM_BYTES (FL_SMEM_FLOATS * 4)       // 84480

__global__ void __launch_bounds__(128) flash_kernel()
{
    extern __shared__ float sm[];
    float* Qs = sm + FL_QS_OFF;
    float* Ks = sm + FL_KS_OFF;
    float* Vs = sm + FL_VS_OFF;
    float* Ps = sm + FL_PS_OFF;

    const int qt = blockIdx.x;      // 0..23
    const int h  = blockIdx.y;
    const int t  = threadIdx.x;
    const int tx = t & 7;
    const int ty = t >> 3;

    const float* Q = g_scratch + OFF_Q;
    const float* K = g_scratch + OFF_K;
    const float* V = g_scratch + OFF_V;

    // Load Q tile (96 x 64) transposed into Qs[d][row], pre-scaled by 1/8
    {
        const float4* Qb = (const float4*)(Q + ((size_t)h * SEQ + qt * FL_QT) * HD);
        #pragma unroll
        for (int r = 0; r < 12; r++) {
            int idx = r * 128 + t;
            int row = idx >> 4, c4 = idx & 15;
            float4 v = Qb[idx];
            Qs[(4 * c4 + 0) * FL_SQ + row] = v.x * 0.125f;
            Qs[(4 * c4 + 1) * FL_SQ + row] = v.y * 0.125f;
            Qs[(4 * c4 + 2) * FL_SQ + row] = v.z * 0.125f;
            Qs[(4 * c4 + 3) * FL_SQ + row] = v.w * 0.125f;
        }
    }

    float o[6][8];
    #pragma unroll
    for (int i = 0; i < 6; i++)
        #pragma unroll
        for (int j = 0; j < 8; j++) o[i][j] = 0.f;
    float m[6], l[6];
    #pragma unroll
    for (int i = 0; i < 6; i++) { m[i] = -1e30f; l[i] = 0.f; }

    for (int kt = 0; kt < SEQ; kt += 64) {
        __syncthreads();   // Qs ready (1st iter) / prev PV done with Vs,Ps

        // Load K tile transposed -> Ks[d][krow]; V tile natural -> Vs[krow][d]
        const float4* Kb = (const float4*)(K + ((size_t)h * SEQ + kt) * HD);
        const float4* Vb = (const float4*)(V + ((size_t)h * SEQ + kt) * HD);
        #pragma unroll
        for (int r = 0; r < 8; r++) {
            int idx = r * 128 + t;
            int row = idx >> 4, c4 = idx & 15;
            float4 kv = Kb[idx];
            Ks[(4 * c4 + 0) * FL_SK + row] = kv.x;
            Ks[(4 * c4 + 1) * FL_SK + row] = kv.y;
            Ks[(4 * c4 + 2) * FL_SK + row] = kv.z;
            Ks[(4 * c4 + 3) * FL_SK + row] = kv.w;
            *(float4*)(Vs + row * FL_SK + c4 * 4) = Vb[idx];
        }
        __syncthreads();

        // ---- QK^T outer-product: S[i][j] = q_i . k_j ----
        float S[6][8];
        #pragma unroll
        for (int i = 0; i < 6; i++)
            #pragma unroll
            for (int j = 0; j < 8; j++) S[i][j] = 0.f;

        #pragma unroll 4
        for (int d = 0; d < 64; d++) {
            float ar[6];
            const float* qd = Qs + d * FL_SQ + ty * 6;
            #pragma unroll
            for (int i = 0; i < 6; i++) ar[i] = qd[i];
            float4 b0 = *(const float4*)(Ks + d * FL_SK + tx * 8);
            float4 b1 = *(const float4*)(Ks + d * FL_SK + tx * 8 + 4);
            float br[8] = {b0.x, b0.y, b0.z, b0.w, b1.x, b1.y, b1.z, b1.w};
            #pragma unroll
            for (int i = 0; i < 6; i++)
                #pragma unroll
                for (int j = 0; j < 8; j++)
                    S[i][j] = fmaf(ar[i], br[j], S[i][j]);
        }

        // ---- Online softmax (row stats across the 8-thread tx group) ----
        #pragma unroll
        for (int i = 0; i < 6; i++) {
            float mt = S[i][0];
            #pragma unroll
            for (int j = 1; j < 8; j++) mt = fmaxf(mt, S[i][j]);
            mt = fmaxf(mt, __shfl_xor_sync(0xffffffffu, mt, 1));
            mt = fmaxf(mt, __shfl_xor_sync(0xffffffffu, mt, 2));
            mt = fmaxf(mt, __shfl_xor_sync(0xffffffffu, mt, 4));
            float mn = fmaxf(m[i], mt);
            float alpha = __expf(m[i] - mn);
            m[i] = mn;
            l[i] *= alpha;
            #pragma unroll
            for (int j = 0; j < 8; j++) o[i][j] *= alpha;

            float rs = 0.f;
            #pragma unroll
            for (int j = 0; j < 8; j++) {
                S[i][j] = __expf(S[i][j] - mn);
                rs += S[i][j];
            }
            rs += __shfl_xor_sync(0xffffffffu, rs, 1);
            rs += __shfl_xor_sync(0xffffffffu, rs, 2);
            rs += __shfl_xor_sync(0xffffffffu, rs, 4);
            l[i] += rs;

            // write P transposed: Ps[kcol][qrow]
            #pragma unroll
            for (int j = 0; j < 8; j++)
                Ps[(tx * 8 + j) * FL_SQ + ty * 6 + i] = S[i][j];
        }
        __syncthreads();

        // ---- PV outer-product: o[i][d] += sum_k P[i][k] * V[k][d] ----
        #pragma unroll 4
        for (int k = 0; k < 64; k++) {
            float ar[6];
            const float* pd = Ps + k * FL_SQ + ty * 6;
            #pragma unroll
            for (int i = 0; i < 6; i++) ar[i] = pd[i];
            float4 b0 = *(const float4*)(Vs + k * FL_SK + tx * 8);
            float4 b1 = *(const float4*)(Vs + k * FL_SK + tx * 8 + 4);
            float br[8] = {b0.x, b0.y, b0.z, b0.w, b1.x, b1.y, b1.z, b1.w};
            #pragma unroll
            for (int i = 0; i < 6; i++)
                #pragma unroll
                for (int j = 0; j < 8; j++)
                    o[i][j] = fmaf(ar[i], br[j], o[i][j]);
        }
    }

    // ---- Epilogue: normalize, write O[s][h*64 + d] ----
    #pragma unroll
    for (int i = 0; i < 6; i++) {
        float li = 1.f / l[i];
        float* op = g_scratch + OFF_O
                  + (size_t)(qt * FL_QT + ty * 6 + i) * DIM + h * HD + tx * 8;
        *(float4*)(op)     = make_float4(o[i][0] * li, o[i][1] * li,
                                         o[i][2] * li, o[i][3] * li);
        *(float4*)(op + 4) = make_float4(o[i][4] * li, o[i][5] * li,
                                         o[i][6] * li, o[i][7] * li);
    }
}

// ---------------------------------------------------------------------------
// Launch
// ---------------------------------------------------------------------------
extern "C" void kernel_launch(void* const* d_in, const int* in_sizes, int n_in,
                              void* d_out, int out_size)
{
    const float* x0     = (const float*)d_in[0];
    const float* x1     = (const float*)d_in[1];
    const float* w_qkv0 = (const float*)d_in[2];
    const float* w_qkv1 = (const float*)d_in[3];
    const float* w_out0 = (const float*)d_in[4];
    const float* w_out1 = (const float*)d_in[5];
    const float* gq0    = (const float*)d_in[6];
    const float* gk0    = (const float*)d_in[7];
    const float* gq1    = (const float*)d_in[8];
    const float* gk1    = (const float*)d_in[9];
    float* out = (float*)d_out;

    float* scratch = nullptr;
    cudaGetSymbolAddress((void**)&scratch, g_scratch);

    static bool attr_set = false;
    if (!attr_set) {
        cudaFuncSetAttribute(flash_kernel,
                             cudaFuncAttributeMaxDynamicSharedMemorySize,
                             FL_SMEM_BYTES);
        attr_set = true;
    }

    // 1) QKV projections
    sgemm128<<<dim3(QKV_N / 128, S0 / 128), 256>>>(x0, w_qkv0, scratch + OFF_QKV0, QKV_N, DIM);
    sgemm128<<<dim3(QKV_N / 128, S1 / 128), 256>>>(x1, w_qkv1, scratch + OFF_QKV1, QKV_N, DIM);

    // 2) RMSNorm + RoPE + scatter to (H, SEQ, HD)
    norm_rope_kernel<<<dim3(SEQ, NH), 32>>>(gq0, gk0, gq1, gk1);

    // 3) Flash attention -> O[SEQ, H*D]
    flash_kernel<<<dim3(SEQ / FL_QT, NH), 128, FL_SMEM_BYTES>>>();

    // 4) Output projections
    sgemm128<<<dim3(DIM / 128, S0 / 128), 256>>>(scratch + OFF_O, w_out0, out, DIM, DIM);
    sgemm128<<<dim3(DIM / 128, S1 / 128), 256>>>(scratch + OFF_O + (size_t)S0 * DIM,
                                                 w_out1, out + (size_t)S0 * DIM, DIM, DIM);
}

// round 15
// speedup vs baseline: 1.0029x; 1.0029x over previous
#include <cuda_runtime.h>

// ---------------------------------------------------------------------------
// Problem constants
// ---------------------------------------------------------------------------
#define S0    2048
#define S1    256
#define SEQ   2304          // S0 + S1
#define DIM   1536          // model dim == H*D
#define NH    24
#define HD    64
#define QKV_N 4608          // 3 * NH * HD

// ---------------------------------------------------------------------------
// Scratch
// ---------------------------------------------------------------------------
#define OFF_QKV0 0u
#define OFF_QKV1 9437184u
#define OFF_Q    10616832u
#define OFF_K    14155776u
#define OFF_V    17694720u
#define OFF_O    21233664u
#define SCRATCH_FLOATS 24772608u

__device__ float g_scratch[SCRATCH_FLOATS];

// ---------------------------------------------------------------------------
// SGEMM: C[M,N] = A[M,K] @ B[K,N], row-major fp32.
// BM=BN=128, BK=8, 256 threads, 8x8 microtile, double-buffered smem.
// ---------------------------------------------------------------------------
__global__ void __launch_bounds__(256) sgemm128(
    const float* __restrict__ A, const float* __restrict__ B,
    float* __restrict__ C, int N, int K)
{
    __shared__ float As[2][8][128];   // transposed A tile
    __shared__ float Bs[2][8][128];

    const int tid = threadIdx.x;
    const int tx = tid & 15;
    const int ty = tid >> 4;

    const float* Ab = A + (size_t)blockIdx.y * 128 * K;
    const float* Bb = B + (size_t)blockIdx.x * 128;

    const int aRow = tid >> 1;
    const int aCol = (tid & 1) * 4;
    const int bRow = tid >> 5;
    const int bCol = (tid & 31) * 4;

    float acc[8][8];
    #pragma unroll
    for (int i = 0; i < 8; i++)
        #pragma unroll
        for (int j = 0; j < 8; j++) acc[i][j] = 0.f;

    {
        float4 av = *(const float4*)(Ab + (size_t)aRow * K + aCol);
        As[0][aCol + 0][aRow] = av.x;
        As[0][aCol + 1][aRow] = av.y;
        As[0][aCol + 2][aRow] = av.z;
        As[0][aCol + 3][aRow] = av.w;
        float4 bv = *(const float4*)(Bb + (size_t)bRow * N + bCol);
        *(float4*)(&Bs[0][bRow][bCol]) = bv;
    }
    __syncthreads();

    int cur = 0;
    for (int k0 = 0; k0 < K; k0 += 8) {
        const bool has_next = (k0 + 8 < K);
        float4 av, bv;
        if (has_next) {
            av = *(const float4*)(Ab + (size_t)aRow * K + (k0 + 8) + aCol);
            bv = *(const float4*)(Bb + (size_t)(k0 + 8 + bRow) * N + bCol);
        }

        #pragma unroll
        for (int k = 0; k < 8; k++) {
            float ar[8], br[8];
            #pragma unroll
            for (int i = 0; i < 8; i++) ar[i] = As[cur][k][ty * 8 + i];
            #pragma unroll
            for (int j = 0; j < 8; j++) br[j] = Bs[cur][k][tx * 8 + j];
            #pragma unroll
            for (int i = 0; i < 8; i++)
                #pragma unroll
                for (int j = 0; j < 8; j++)
                    acc[i][j] = fmaf(ar[i], br[j], acc[i][j]);
        }

        if (has_next) {
            As[cur ^ 1][aCol + 0][aRow] = av.x;
            As[cur ^ 1][aCol + 1][aRow] = av.y;
            As[cur ^ 1][aCol + 2][aRow] = av.z;
            As[cur ^ 1][aCol + 3][aRow] = av.w;
            *(float4*)(&Bs[cur ^ 1][bRow][bCol]) = bv;
        }
        __syncthreads();
        cur ^= 1;
    }

    #pragma unroll
    for (int i = 0; i < 8; i++) {
        float* Crow = C + (size_t)(blockIdx.y * 128 + ty * 8 + i) * N
                        + blockIdx.x * 128 + tx * 8;
        *(float4*)(Crow)     = make_float4(acc[i][0], acc[i][1], acc[i][2], acc[i][3]);
        *(float4*)(Crow + 4) = make_float4(acc[i][4], acc[i][5], acc[i][6], acc[i][7]);
    }
}

// ---------------------------------------------------------------------------
// RMSNorm + RoPE + scatter to (H, SEQ, HD) Q/K/V. One warp per (s, head).
// ---------------------------------------------------------------------------
__global__ void norm_rope_kernel(
    const float* __restrict__ gq0, const float* __restrict__ gk0,
    const float* __restrict__ gq1, const float* __restrict__ gk1)
{
    const int s = blockIdx.x;
    const int h = blockIdx.y;
    const int d = threadIdx.x;     // 0..31

    const float* src;
    const float *gq, *gk;
    int pos;
    if (s < S0) {
        pos = s;
        src = g_scratch + OFF_QKV0 + (size_t)s * QKV_N;
        gq = gq0; gk = gk0;
    } else {
        pos = s - S0;
        src = g_scratch + OFF_QKV1 + (size_t)pos * QKV_N;
        gq = gq1; gk = gk1;
    }

    const int col = h * HD + d;
    float qa = src[col],            qb = src[col + 32];
    float ka = src[DIM + col],      kb = src[DIM + col + 32];
    float va = src[2 * DIM + col],  vb = src[2 * DIM + col + 32];

    float ssq = qa * qa + qb * qb;
    float ssk = ka * ka + kb * kb;
    #pragma unroll
    for (int o = 16; o; o >>= 1) {
        ssq += __shfl_xor_sync(0xffffffffu, ssq, o);
        ssk += __shfl_xor_sync(0xffffffffu, ssk, o);
    }
    float rq = rsqrtf(ssq * (1.f / 64.f) + 1e-6f);
    float rk = rsqrtf(ssk * (1.f / 64.f) + 1e-6f);
    qa *= rq * gq[d]; qb *= rq * gq[d + 32];
    ka *= rk * gk[d]; kb *= rk * gk[d + 32];

    float inv = powf(10000.f, -(float)(2 * d) * (1.f / 64.f));
    float f = (float)pos * inv;
    float sn, cs;
    sincosf(f, &sn, &cs);
    float qoa = qa * cs - qb * sn, qob = qb * cs + qa * sn;
    float koa = ka * cs - kb * sn, kob = kb * cs + ka * sn;

    const size_t base = ((size_t)h * SEQ + s) * HD;
    g_scratch[OFF_Q + base + d]      = qoa;
    g_scratch[OFF_Q + base + d + 32] = qob;
    g_scratch[OFF_K + base + d]      = koa;
    g_scratch[OFF_K + base + d + 32] = kob;
    g_scratch[OFF_V + base + d]      = va;
    g_scratch[OFF_V + base + d + 32] = vb;
}

// ---------------------------------------------------------------------------
// Flash attention v3: register-blocked (GEMM-style outer products).
// Block = (96-row q-tile, head), 128 threads.
// Thread (ty,tx) with ty=t>>3 (0..15), tx=t&7 (0..7) owns a 6x8 microtile:
//   q-rows  i = ty*6 + 0..5
//   k-cols  j = tx*8 + 0..7  (QK phase) / dims d = tx*8 + 0..7 (PV phase)
// Q,K in smem d-major (transposed); P transposed [k][row]; V natural [k][d].
// Per d/k step: 6 broadcast scalars + 2 float4 -> 48 FMAs (ratio 3.4).
// Softmax row stats via shfl over the 8-thread tx group (lane bits 0..2).
// Smem: Qs 64x97, Ks 64x68, Vs 64x68, Ps 64x97 = 84480 B (dynamic).
// ---------------------------------------------------------------------------
#define FL_QT   96
#define FL_SQ   97          // Qs/Ps row stride
#define FL_SK   68          // Ks/Vs row stride (float4-aligned)
#define FL_QS_OFF 0
#define FL_KS_OFF (64 * FL_SQ)                 // 6208
#define FL_VS_OFF (FL_KS_OFF + 64 * FL_SK)     // 10560
#define FL_PS_OFF (FL_VS_OFF + 64 * FL_SK)     // 14912
#define FL_SMEM_FLOATS (FL_PS_OFF + 64 * FL_SQ)  // 21120
#define FL_SMEM_BYTES (FL_SMEM_FLOATS * 4)       // 84480

__global__ void __launch_bounds__(128) flash_kernel()
{
    extern __shared__ float sm[];
    float* Qs = sm + FL_QS_OFF;
    float* Ks = sm + FL_KS_OFF;
    float* Vs = sm + FL_VS_OFF;
    float* Ps = sm + FL_PS_OFF;

    const int qt = blockIdx.x;      // 0..23
    const int h  = blockIdx.y;
    const int t  = threadIdx.x;
    const int tx = t & 7;
    const int ty = t >> 3;

    const float* Q = g_scratch + OFF_Q;
    const float* K = g_scratch + OFF_K;
    const float* V = g_scratch + OFF_V;

    // Load Q tile (96 x 64) transposed into Qs[d][row], pre-scaled by 1/8
    {
        const float4* Qb = (const float4*)(Q + ((size_t)h * SEQ + qt * FL_QT) * HD);
        #pragma unroll
        for (int r = 0; r < 12; r++) {
            int idx = r * 128 + t;
            int row = idx >> 4, c4 = idx & 15;
            float4 v = Qb[idx];
            Qs[(4 * c4 + 0) * FL_SQ + row] = v.x * 0.125f;
            Qs[(4 * c4 + 1) * FL_SQ + row] = v.y * 0.125f;
            Qs[(4 * c4 + 2) * FL_SQ + row] = v.z * 0.125f;
            Qs[(4 * c4 + 3) * FL_SQ + row] = v.w * 0.125f;
        }
    }

    float o[6][8];
    #pragma unroll
    for (int i = 0; i < 6; i++)
        #pragma unroll
        for (int j = 0; j < 8; j++) o[i][j] = 0.f;
    float m[6], l[6];
    #pragma unroll
    for (int i = 0; i < 6; i++) { m[i] = -1e30f; l[i] = 0.f; }

    for (int kt = 0; kt < SEQ; kt += 64) {
        __syncthreads();   // Qs ready (1st iter) / prev PV done with Vs,Ps

        // Load K tile transposed -> Ks[d][krow]; V tile natural -> Vs[krow][d]
        const float4* Kb = (const float4*)(K + ((size_t)h * SEQ + kt) * HD);
        const float4* Vb = (const float4*)(V + ((size_t)h * SEQ + kt) * HD);
        #pragma unroll
        for (int r = 0; r < 8; r++) {
            int idx = r * 128 + t;
            int row = idx >> 4, c4 = idx & 15;
            float4 kv = Kb[idx];
            Ks[(4 * c4 + 0) * FL_SK + row] = kv.x;
            Ks[(4 * c4 + 1) * FL_SK + row] = kv.y;
            Ks[(4 * c4 + 2) * FL_SK + row] = kv.z;
            Ks[(4 * c4 + 3) * FL_SK + row] = kv.w;
            *(float4*)(Vs + row * FL_SK + c4 * 4) = Vb[idx];
        }
        __syncthreads();

        // ---- QK^T outer-product: S[i][j] = q_i . k_j ----
        float S[6][8];
        #pragma unroll
        for (int i = 0; i < 6; i++)
            #pragma unroll
            for (int j = 0; j < 8; j++) S[i][j] = 0.f;

        #pragma unroll 4
        for (int d = 0; d < 64; d++) {
            float ar[6];
            const float* qd = Qs + d * FL_SQ + ty * 6;
            #pragma unroll
            for (int i = 0; i < 6; i++) ar[i] = qd[i];
            float4 b0 = *(const float4*)(Ks + d * FL_SK + tx * 8);
            float4 b1 = *(const float4*)(Ks + d * FL_SK + tx * 8 + 4);
            float br[8] = {b0.x, b0.y, b0.z, b0.w, b1.x, b1.y, b1.z, b1.w};
            #pragma unroll
            for (int i = 0; i < 6; i++)
                #pragma unroll
                for (int j = 0; j < 8; j++)
                    S[i][j] = fmaf(ar[i], br[j], S[i][j]);
        }

        // ---- Online softmax (row stats across the 8-thread tx group) ----
        #pragma unroll
        for (int i = 0; i < 6; i++) {
            float mt = S[i][0];
            #pragma unroll
            for (int j = 1; j < 8; j++) mt = fmaxf(mt, S[i][j]);
            mt = fmaxf(mt, __shfl_xor_sync(0xffffffffu, mt, 1));
            mt = fmaxf(mt, __shfl_xor_sync(0xffffffffu, mt, 2));
            mt = fmaxf(mt, __shfl_xor_sync(0xffffffffu, mt, 4));
            float mn = fmaxf(m[i], mt);
            float alpha = __expf(m[i] - mn);
            m[i] = mn;
            l[i] *= alpha;
            #pragma unroll
            for (int j = 0; j < 8; j++) o[i][j] *= alpha;

            float rs = 0.f;
            #pragma unroll
            for (int j = 0; j < 8; j++) {
                S[i][j] = __expf(S[i][j] - mn);
                rs += S[i][j];
            }
            rs += __shfl_xor_sync(0xffffffffu, rs, 1);
            rs += __shfl_xor_sync(0xffffffffu, rs, 2);
            rs += __shfl_xor_sync(0xffffffffu, rs, 4);
            l[i] += rs;

            // write P transposed: Ps[kcol][qrow]
            #pragma unroll
            for (int j = 0; j < 8; j++)
                Ps[(tx * 8 + j) * FL_SQ + ty * 6 + i] = S[i][j];
        }
        __syncthreads();

        // ---- PV outer-product: o[i][d] += sum_k P[i][k] * V[k][d] ----
        #pragma unroll 4
        for (int k = 0; k < 64; k++) {
            float ar[6];
            const float* pd = Ps + k * FL_SQ + ty * 6;
            #pragma unroll
            for (int i = 0; i < 6; i++) ar[i] = pd[i];
            float4 b0 = *(const float4*)(Vs + k * FL_SK + tx * 8);
            float4 b1 = *(const float4*)(Vs + k * FL_SK + tx * 8 + 4);
            float br[8] = {b0.x, b0.y, b0.z, b0.w, b1.x, b1.y, b1.z, b1.w};
            #pragma unroll
            for (int i = 0; i < 6; i++)
                #pragma unroll
                for (int j = 0; j < 8; j++)
                    o[i][j] = fmaf(ar[i], br[j], o[i][j]);
        }
    }

    // ---- Epilogue: normalize, write O[s][h*64 + d] ----
    #pragma unroll
    for (int i = 0; i < 6; i++) {
        float li = 1.f / l[i];
        float* op = g_scratch + OFF_O
                  + (size_t)(qt * FL_QT + ty * 6 + i) * DIM + h * HD + tx * 8;
        *(float4*)(op)     = make_float4(o[i][0] * li, o[i][1] * li,
                                         o[i][2] * li, o[i][3] * li);
        *(float4*)(op + 4) = make_float4(o[i][4] * li, o[i][5] * li,
                                         o[i][6] * li, o[i][7] * li);
    }
}

// ---------------------------------------------------------------------------
// Launch
// ---------------------------------------------------------------------------
extern "C" void kernel_launch(void* const* d_in, const int* in_sizes, int n_in,
                              void* d_out, int out_size)
{
    const float* x0     = (const float*)d_in[0];
    const float* x1     = (const float*)d_in[1];
    const float* w_qkv0 = (const float*)d_in[2];
    const float* w_qkv1 = (const float*)d_in[3];
    const float* w_out0 = (const float*)d_in[4];
    const float* w_out1 = (const float*)d_in[5];
    const float* gq0    = (const float*)d_in[6];
    const float* gk0    = (const float*)d_in[7];
    const float* gq1    = (const float*)d_in[8];
    const float* gk1    = (const float*)d_in[9];
    float* out = (float*)d_out;

    float* scratch = nullptr;
    cudaGetSymbolAddress((void**)&scratch, g_scratch);

    static bool attr_set = false;
    if (!attr_set) {
        cudaFuncSetAttribute(flash_kernel,
                             cudaFuncAttributeMaxDynamicSharedMemorySize,
                             FL_SMEM_BYTES);
        attr_set = true;
    }

    // 1) QKV projections
    sgemm128<<<dim3(QKV_N / 128, S0 / 128), 256>>>(x0, w_qkv0, scratch + OFF_QKV0, QKV_N, DIM);
    sgemm128<<<dim3(QKV_N / 128, S1 / 128), 256>>>(x1, w_qkv1, scratch + OFF_QKV1, QKV_N, DIM);

    // 2) RMSNorm + RoPE + scatter to (H, SEQ, HD)
    norm_rope_kernel<<<dim3(SEQ, NH), 32>>>(gq0, gk0, gq1, gk1);

    // 3) Flash attention -> O[SEQ, H*D]
    flash_kernel<<<dim3(SEQ / FL_QT, NH), 128, FL_SMEM_BYTES>>>();

    // 4) Output projections
    sgemm128<<<dim3(DIM / 128, S0 / 128), 256>>>(scratch + OFF_O, w_out0, out, DIM, DIM);
    sgemm128<<<dim3(DIM / 128, S1 / 128), 256>>>(scratch + OFF_O + (size_t)S0 * DIM,
                                                 w_out1, out + (size_t)S0 * DIM, DIM, DIM);
}

// round 16
// speedup vs baseline: 1.0047x; 1.0018x over previous
#include <cuda_runtime.h>

// ---------------------------------------------------------------------------
// Problem constants
// ---------------------------------------------------------------------------
#define S0    2048
#define S1    256
#define SEQ   2304          // S0 + S1
#define DIM   1536          // model dim == H*D
#define NH    24
#define HD    64
#define QKV_N 4608          // 3 * NH * HD

// ---------------------------------------------------------------------------
// Scratch
// ---------------------------------------------------------------------------
#define OFF_QKV0 0u
#define OFF_QKV1 9437184u
#define OFF_Q    10616832u
#define OFF_K    14155776u
#define OFF_V    17694720u
#define OFF_O    21233664u
#define SCRATCH_FLOATS 24772608u

__device__ float g_scratch[SCRATCH_FLOATS];

// ---------------------------------------------------------------------------
// SGEMM: C[M,N] = A[M,K] @ B[K,N], row-major fp32.
// BM=BN=128, BK=8, 256 threads, 8x8 microtile, double-buffered smem.
// ---------------------------------------------------------------------------
__global__ void __launch_bounds__(256) sgemm128(
    const float* __restrict__ A, const float* __restrict__ B,
    float* __restrict__ C, int N, int K)
{
    __shared__ float As[2][8][128];   // transposed A tile
    __shared__ float Bs[2][8][128];

    const int tid = threadIdx.x;
    const int tx = tid & 15;
    const int ty = tid >> 4;

    const float* Ab = A + (size_t)blockIdx.y * 128 * K;
    const float* Bb = B + (size_t)blockIdx.x * 128;

    const int aRow = tid >> 1;
    const int aCol = (tid & 1) * 4;
    const int bRow = tid >> 5;
    const int bCol = (tid & 31) * 4;

    float acc[8][8];
    #pragma unroll
    for (int i = 0; i < 8; i++)
        #pragma unroll
        for (int j = 0; j < 8; j++) acc[i][j] = 0.f;

    {
        float4 av = *(const float4*)(Ab + (size_t)aRow * K + aCol);
        As[0][aCol + 0][aRow] = av.x;
        As[0][aCol + 1][aRow] = av.y;
        As[0][aCol + 2][aRow] = av.z;
        As[0][aCol + 3][aRow] = av.w;
        float4 bv = *(const float4*)(Bb + (size_t)bRow * N + bCol);
        *(float4*)(&Bs[0][bRow][bCol]) = bv;
    }
    __syncthreads();

    int cur = 0;
    for (int k0 = 0; k0 < K; k0 += 8) {
        const bool has_next = (k0 + 8 < K);
        float4 av, bv;
        if (has_next) {
            av = *(const float4*)(Ab + (size_t)aRow * K + (k0 + 8) + aCol);
            bv = *(const float4*)(Bb + (size_t)(k0 + 8 + bRow) * N + bCol);
        }

        #pragma unroll
        for (int k = 0; k < 8; k++) {
            float ar[8], br[8];
            #pragma unroll
            for (int i = 0; i < 8; i++) ar[i] = As[cur][k][ty * 8 + i];
            #pragma unroll
            for (int j = 0; j < 8; j++) br[j] = Bs[cur][k][tx * 8 + j];
            #pragma unroll
            for (int i = 0; i < 8; i++)
                #pragma unroll
                for (int j = 0; j < 8; j++)
                    acc[i][j] = fmaf(ar[i], br[j], acc[i][j]);
        }

        if (has_next) {
            As[cur ^ 1][aCol + 0][aRow] = av.x;
            As[cur ^ 1][aCol + 1][aRow] = av.y;
            As[cur ^ 1][aCol + 2][aRow] = av.z;
            As[cur ^ 1][aCol + 3][aRow] = av.w;
            *(float4*)(&Bs[cur ^ 1][bRow][bCol]) = bv;
        }
        __syncthreads();
        cur ^= 1;
    }

    #pragma unroll
    for (int i = 0; i < 8; i++) {
        float* Crow = C + (size_t)(blockIdx.y * 128 + ty * 8 + i) * N
                        + blockIdx.x * 128 + tx * 8;
        *(float4*)(Crow)     = make_float4(acc[i][0], acc[i][1], acc[i][2], acc[i][3]);
        *(float4*)(Crow + 4) = make_float4(acc[i][4], acc[i][5], acc[i][6], acc[i][7]);
    }
}

// ---------------------------------------------------------------------------
// RMSNorm + RoPE + scatter to (H, SEQ, HD) Q/K/V. One warp per (s, head).
// ---------------------------------------------------------------------------
__global__ void norm_rope_kernel(
    const float* __restrict__ gq0, const float* __restrict__ gk0,
    const float* __restrict__ gq1, const float* __restrict__ gk1)
{
    const int s = blockIdx.x;
    const int h = blockIdx.y;
    const int d = threadIdx.x;     // 0..31

    const float* src;
    const float *gq, *gk;
    int pos;
    if (s < S0) {
        pos = s;
        src = g_scratch + OFF_QKV0 + (size_t)s * QKV_N;
        gq = gq0; gk = gk0;
    } else {
        pos = s - S0;
        src = g_scratch + OFF_QKV1 + (size_t)pos * QKV_N;
        gq = gq1; gk = gk1;
    }

    const int col = h * HD + d;
    float qa = src[col],            qb = src[col + 32];
    float ka = src[DIM + col],      kb = src[DIM + col + 32];
    float va = src[2 * DIM + col],  vb = src[2 * DIM + col + 32];

    float ssq = qa * qa + qb * qb;
    float ssk = ka * ka + kb * kb;
    #pragma unroll
    for (int o = 16; o; o >>= 1) {
        ssq += __shfl_xor_sync(0xffffffffu, ssq, o);
        ssk += __shfl_xor_sync(0xffffffffu, ssk, o);
    }
    float rq = rsqrtf(ssq * (1.f / 64.f) + 1e-6f);
    float rk = rsqrtf(ssk * (1.f / 64.f) + 1e-6f);
    qa *= rq * gq[d]; qb *= rq * gq[d + 32];
    ka *= rk * gk[d]; kb *= rk * gk[d + 32];

    float inv = powf(10000.f, -(float)(2 * d) * (1.f / 64.f));
    float f = (float)pos * inv;
    float sn, cs;
    sincosf(f, &sn, &cs);
    float qoa = qa * cs - qb * sn, qob = qb * cs + qa * sn;
    float koa = ka * cs - kb * sn, kob = kb * cs + ka * sn;

    const size_t base = ((size_t)h * SEQ + s) * HD;
    g_scratch[OFF_Q + base + d]      = qoa;
    g_scratch[OFF_Q + base + d + 32] = qob;
    g_scratch[OFF_K + base + d]      = koa;
    g_scratch[OFF_K + base + d + 32] = kob;
    g_scratch[OFF_V + base + d]      = va;
    g_scratch[OFF_V + base + d + 32] = vb;
}

// ---------------------------------------------------------------------------
// Flash attention v3: register-blocked (GEMM-style outer products).
// Block = (96-row q-tile, head), 128 threads.
// Thread (ty,tx) with ty=t>>3 (0..15), tx=t&7 (0..7) owns a 6x8 microtile:
//   q-rows  i = ty*6 + 0..5
//   k-cols  j = tx*8 + 0..7  (QK phase) / dims d = tx*8 + 0..7 (PV phase)
// Q,K in smem d-major (transposed); P transposed [k][row]; V natural [k][d].
// Per d/k step: 6 broadcast scalars + 2 float4 -> 48 FMAs (ratio 3.4).
// Softmax row stats via shfl over the 8-thread tx group (lane bits 0..2).
// Smem: Qs 64x97, Ks 64x68, Vs 64x68, Ps 64x97 = 84480 B (dynamic).
// ---------------------------------------------------------------------------
#define FL_QT   96
#define FL_SQ   97          // Qs/Ps row stride
#define FL_SK   68          // Ks/Vs row stride (float4-aligned)
#define FL_QS_OFF 0
#define FL_KS_OFF (64 * FL_SQ)                 // 6208
#define FL_VS_OFF (FL_KS_OFF + 64 * FL_SK)     // 10560
#define FL_PS_OFF (FL_VS_OFF + 64 * FL_SK)     // 14912
#define FL_SMEM_FLOATS (FL_PS_OFF + 64 * FL_SQ)  // 21120
#define FL_SMEM_BYTES (FL_SMEM_FLOATS * 4)       // 84480

__global__ void __launch_bounds__(128) flash_kernel()
{
    extern __shared__ float sm[];
    float* Qs = sm + FL_QS_OFF;
    float* Ks = sm + FL_KS_OFF;
    float* Vs = sm + FL_VS_OFF;
    float* Ps = sm + FL_PS_OFF;

    const int qt = blockIdx.x;      // 0..23
    const int h  = blockIdx.y;
    const int t  = threadIdx.x;
    const int tx = t & 7;
    const int ty = t >> 3;

    const float* Q = g_scratch + OFF_Q;
    const float* K = g_scratch + OFF_K;
    const float* V = g_scratch + OFF_V;

    // Load Q tile (96 x 64) transposed into Qs[d][row], pre-scaled by 1/8
    {
        const float4* Qb = (const float4*)(Q + ((size_t)h * SEQ + qt * FL_QT) * HD);
        #pragma unroll
        for (int r = 0; r < 12; r++) {
            int idx = r * 128 + t;
            int row = idx >> 4, c4 = idx & 15;
            float4 v = Qb[idx];
            Qs[(4 * c4 + 0) * FL_SQ + row] = v.x * 0.125f;
            Qs[(4 * c4 + 1) * FL_SQ + row] = v.y * 0.125f;
            Qs[(4 * c4 + 2) * FL_SQ + row] = v.z * 0.125f;
            Qs[(4 * c4 + 3) * FL_SQ + row] = v.w * 0.125f;
        }
    }

    float o[6][8];
    #pragma unroll
    for (int i = 0; i < 6; i++)
        #pragma unroll
        for (int j = 0; j < 8; j++) o[i][j] = 0.f;
    float m[6], l[6];
    #pragma unroll
    for (int i = 0; i < 6; i++) { m[i] = -1e30f; l[i] = 0.f; }

    for (int kt = 0; kt < SEQ; kt += 64) {
        __syncthreads();   // Qs ready (1st iter) / prev PV done with Vs,Ps

        // Load K tile transposed -> Ks[d][krow]; V tile natural -> Vs[krow][d]
        const float4* Kb = (const float4*)(K + ((size_t)h * SEQ + kt) * HD);
        const float4* Vb = (const float4*)(V + ((size_t)h * SEQ + kt) * HD);
        #pragma unroll
        for (int r = 0; r < 8; r++) {
            int idx = r * 128 + t;
            int row = idx >> 4, c4 = idx & 15;
            float4 kv = Kb[idx];
            Ks[(4 * c4 + 0) * FL_SK + row] = kv.x;
            Ks[(4 * c4 + 1) * FL_SK + row] = kv.y;
            Ks[(4 * c4 + 2) * FL_SK + row] = kv.z;
            Ks[(4 * c4 + 3) * FL_SK + row] = kv.w;
            *(float4*)(Vs + row * FL_SK + c4 * 4) = Vb[idx];
        }
        __syncthreads();

        // ---- QK^T outer-product: S[i][j] = q_i . k_j ----
        float S[6][8];
        #pragma unroll
        for (int i = 0; i < 6; i++)
            #pragma unroll
            for (int j = 0; j < 8; j++) S[i][j] = 0.f;

        #pragma unroll 4
        for (int d = 0; d < 64; d++) {
            float ar[6];
            const float* qd = Qs + d * FL_SQ + ty * 6;
            #pragma unroll
            for (int i = 0; i < 6; i++) ar[i] = qd[i];
            float4 b0 = *(const float4*)(Ks + d * FL_SK + tx * 8);
            float4 b1 = *(const float4*)(Ks + d * FL_SK + tx * 8 + 4);
            float br[8] = {b0.x, b0.y, b0.z, b0.w, b1.x, b1.y, b1.z, b1.w};
            #pragma unroll
            for (int i = 0; i < 6; i++)
                #pragma unroll
                for (int j = 0; j < 8; j++)
                    S[i][j] = fmaf(ar[i], br[j], S[i][j]);
        }

        // ---- Online softmax (row stats across the 8-thread tx group) ----
        #pragma unroll
        for (int i = 0; i < 6; i++) {
            float mt = S[i][0];
            #pragma unroll
            for (int j = 1; j < 8; j++) mt = fmaxf(mt, S[i][j]);
            mt = fmaxf(mt, __shfl_xor_sync(0xffffffffu, mt, 1));
            mt = fmaxf(mt, __shfl_xor_sync(0xffffffffu, mt, 2));
            mt = fmaxf(mt, __shfl_xor_sync(0xffffffffu, mt, 4));
            float mn = fmaxf(m[i], mt);
            float alpha = __expf(m[i] - mn);
            m[i] = mn;
            l[i] *= alpha;
            #pragma unroll
            for (int j = 0; j < 8; j++) o[i][j] *= alpha;

            float rs = 0.f;
            #pragma unroll
            for (int j = 0; j < 8; j++) {
                S[i][j] = __expf(S[i][j] - mn);
                rs += S[i][j];
            }
            rs += __shfl_xor_sync(0xffffffffu, rs, 1);
            rs += __shfl_xor_sync(0xffffffffu, rs, 2);
            rs += __shfl_xor_sync(0xffffffffu, rs, 4);
            l[i] += rs;

            // write P transposed: Ps[kcol][qrow]
            #pragma unroll
            for (int j = 0; j < 8; j++)
                Ps[(tx * 8 + j) * FL_SQ + ty * 6 + i] = S[i][j];
        }
        __syncthreads();

        // ---- PV outer-product: o[i][d] += sum_k P[i][k] * V[k][d] ----
        #pragma unroll 4
        for (int k = 0; k < 64; k++) {
            float ar[6];
            const float* pd = Ps + k * FL_SQ + ty * 6;
            #pragma unroll
            for (int i = 0; i < 6; i++) ar[i] = pd[i];
            float4 b0 = *(const float4*)(Vs + k * FL_SK + tx * 8);
            float4 b1 = *(const float4*)(Vs + k * FL_SK + tx * 8 + 4);
            float br[8] = {b0.x, b0.y, b0.z, b0.w, b1.x, b1.y, b1.z, b1.w};
            #pragma unroll
            for (int i = 0; i < 6; i++)
                #pragma unroll
                for (int j = 0; j < 8; j++)
                    o[i][j] = fmaf(ar[i], br[j], o[i][j]);
        }
    }

    // ---- Epilogue: normalize, write O[s][h*64 + d] ----
    #pragma unroll
    for (int i = 0; i < 6; i++) {
        float li = 1.f / l[i];
        float* op = g_scratch + OFF_O
                  + (size_t)(qt * FL_QT + ty * 6 + i) * DIM + h * HD + tx * 8;
        *(float4*)(op)     = make_float4(o[i][0] * li, o[i][1] * li,
                                         o[i][2] * li, o[i][3] * li);
        *(float4*)(op + 4) = make_float4(o[i][4] * li, o[i][5] * li,
                                         o[i][6] * li, o[i][7] * li);
    }
}

// ---------------------------------------------------------------------------
// Launch
// ---------------------------------------------------------------------------
extern "C" void kernel_launch(void* const* d_in, const int* in_sizes, int n_in,
                              void* d_out, int out_size)
{
    const float* x0     = (const float*)d_in[0];
    const float* x1     = (const float*)d_in[1];
    const float* w_qkv0 = (const float*)d_in[2];
    const float* w_qkv1 = (const float*)d_in[3];
    const float* w_out0 = (const float*)d_in[4];
    const float* w_out1 = (const float*)d_in[5];
    const float* gq0    = (const float*)d_in[6];
    const float* gk0    = (const float*)d_in[7];
    const float* gq1    = (const float*)d_in[8];
    const float* gk1    = (const float*)d_in[9];
    float* out = (float*)d_out;

    float* scratch = nullptr;
    cudaGetSymbolAddress((void**)&scratch, g_scratch);

    static bool attr_set = false;
    if (!attr_set) {
        cudaFuncSetAttribute(flash_kernel,
                             cudaFuncAttributeMaxDynamicSharedMemorySize,
                             FL_SMEM_BYTES);
        attr_set = true;
    }

    // 1) QKV projections
    sgemm128<<<dim3(QKV_N / 128, S0 / 128), 256>>>(x0, w_qkv0, scratch + OFF_QKV0, QKV_N, DIM);
    sgemm128<<<dim3(QKV_N / 128, S1 / 128), 256>>>(x1, w_qkv1, scratch + OFF_QKV1, QKV_N, DIM);

    // 2) RMSNorm + RoPE + scatter to (H, SEQ, HD)
    norm_rope_kernel<<<dim3(SEQ, NH), 32>>>(gq0, gk0, gq1, gk1);

    // 3) Flash attention -> O[SEQ, H*D]
    flash_kernel<<<dim3(SEQ / FL_QT, NH), 128, FL_SMEM_BYTES>>>();

    // 4) Output projections
    sgemm128<<<dim3(DIM / 128, S0 / 128), 256>>>(scratch + OFF_O, w_out0, out, DIM, DIM);
    sgemm128<<<dim3(DIM / 128, S1 / 128), 256>>>(scratch + OFF_O + (size_t)S0 * DIM,
                                                 w_out1, out + (size_t)S0 * DIM, DIM, DIM);
}

// round 17
// speedup vs baseline: 1.1226x; 1.1173x over previous
#include <cuda_runtime.h>

// ---------------------------------------------------------------------------
// Problem constants
// ---------------------------------------------------------------------------
#define S0    2048
#define S1    256
#define SEQ   2304          // S0 + S1
#define DIM   1536          // model dim == H*D
#define NH    24
#define HD    64
#define QKV_N 4608          // 3 * NH * HD

// ---------------------------------------------------------------------------
// Scratch
// ---------------------------------------------------------------------------
#define OFF_QKV0 0u
#define OFF_QKV1 9437184u
#define OFF_Q    10616832u   // Q transposed: [h][d][s]
#define OFF_K    14155776u   // K transposed: [h][d][s]
#define OFF_V    17694720u   // V natural:    [h][s][d]
#define OFF_O    21233664u
#define SCRATCH_FLOATS 24772608u

__device__ float g_scratch[SCRATCH_FLOATS];

// ---------------------------------------------------------------------------
// Packed f32x2 helpers (Blackwell FFMA2 — ptxas never emits these from C++)
// ---------------------------------------------------------------------------
typedef unsigned long long ull;

__device__ __forceinline__ ull pk2(float x, float y) {
    ull r;
    asm("mov.b64 %0, {%1, %2};" : "=l"(r) : "f"(x), "f"(y));
    return r;
}
__device__ __forceinline__ void upk2(float& x, float& y, ull v) {
    asm("mov.b64 {%0, %1}, %2;" : "=f"(x), "=f"(y) : "l"(v));
}
__device__ __forceinline__ ull fma2(ull a, ull b, ull c) {
    ull d;
    asm("fma.rn.f32x2 %0, %1, %2, %3;" : "=l"(d) : "l"(a), "l"(b), "l"(c));
    return d;
}
__device__ __forceinline__ ull mul2(ull a, ull b) {
    ull d;
    asm("mul.rn.f32x2 %0, %1, %2;" : "=l"(d) : "l"(a), "l"(b));
    return d;
}

// ---------------------------------------------------------------------------
// SGEMM: C[M,N] = A[M,K] @ B[K,N], row-major fp32, FFMA2 inner loop.
// BM=BN=128, BK=8, 256 threads, 8x8 microtile, double-buffered smem.
// ---------------------------------------------------------------------------
__global__ void __launch_bounds__(256) sgemm128(
    const float* __restrict__ A, const float* __restrict__ B,
    float* __restrict__ C, int N, int K)
{
    __shared__ float As[2][8][128];   // transposed A tile
    __shared__ float Bs[2][8][128];

    const int tid = threadIdx.x;
    const int tx = tid & 15;
    const int ty = tid >> 4;

    const float* Ab = A + (size_t)blockIdx.y * 128 * K;
    const float* Bb = B + (size_t)blockIdx.x * 128;

    const int aRow = tid >> 1;
    const int aCol = (tid & 1) * 4;
    const int bRow = tid >> 5;
    const int bCol = (tid & 31) * 4;

    ull acc2[8][4];
    #pragma unroll
    for (int i = 0; i < 8; i++)
        #pragma unroll
        for (int j = 0; j < 4; j++) acc2[i][j] = 0ull;

    {
        float4 av = *(const float4*)(Ab + (size_t)aRow * K + aCol);
        As[0][aCol + 0][aRow] = av.x;
        As[0][aCol + 1][aRow] = av.y;
        As[0][aCol + 2][aRow] = av.z;
        As[0][aCol + 3][aRow] = av.w;
        float4 bv = *(const float4*)(Bb + (size_t)bRow * N + bCol);
        *(float4*)(&Bs[0][bRow][bCol]) = bv;
    }
    __syncthreads();

    int cur = 0;
    for (int k0 = 0; k0 < K; k0 += 8) {
        const bool has_next = (k0 + 8 < K);
        float4 av, bv;
        if (has_next) {
            av = *(const float4*)(Ab + (size_t)aRow * K + (k0 + 8) + aCol);
            bv = *(const float4*)(Bb + (size_t)(k0 + 8 + bRow) * N + bCol);
        }

        #pragma unroll
        for (int k = 0; k < 8; k++) {
            float4 a0 = *(const float4*)(&As[cur][k][ty * 8]);
            float4 a1 = *(const float4*)(&As[cur][k][ty * 8 + 4]);
            float4 b0 = *(const float4*)(&Bs[cur][k][tx * 8]);
            float4 b1 = *(const float4*)(&Bs[cur][k][tx * 8 + 4]);
            ull bb[4] = {pk2(b0.x, b0.y), pk2(b0.z, b0.w),
                         pk2(b1.x, b1.y), pk2(b1.z, b1.w)};
            float ar[8] = {a0.x, a0.y, a0.z, a0.w, a1.x, a1.y, a1.z, a1.w};
            #pragma unroll
            for (int i = 0; i < 8; i++) {
                ull aa = pk2(ar[i], ar[i]);
                #pragma unroll
                for (int j = 0; j < 4; j++)
                    acc2[i][j] = fma2(aa, bb[j], acc2[i][j]);
            }
        }

        if (has_next) {
            As[cur ^ 1][aCol + 0][aRow] = av.x;
            As[cur ^ 1][aCol + 1][aRow] = av.y;
            As[cur ^ 1][aCol + 2][aRow] = av.z;
            As[cur ^ 1][aCol + 3][aRow] = av.w;
            *(float4*)(&Bs[cur ^ 1][bRow][bCol]) = bv;
        }
        __syncthreads();
        cur ^= 1;
    }

    #pragma unroll
    for (int i = 0; i < 8; i++) {
        float c0, c1, c2, c3, c4, c5, c6, c7;
        upk2(c0, c1, acc2[i][0]);
        upk2(c2, c3, acc2[i][1]);
        upk2(c4, c5, acc2[i][2]);
        upk2(c6, c7, acc2[i][3]);
        float* Crow = C + (size_t)(blockIdx.y * 128 + ty * 8 + i) * N
                        + blockIdx.x * 128 + tx * 8;
        *(float4*)(Crow)     = make_float4(c0, c1, c2, c3);
        *(float4*)(Crow + 4) = make_float4(c4, c5, c6, c7);
    }
}

// ---------------------------------------------------------------------------
// RMSNorm + RoPE. Writes Q,K TRANSPOSED ([h][d][s]) so flash can stage its
// K/Q smem tiles with coalesced vector stores (no transposing STS conflicts).
// V stays [h][s][d]. One warp per (s, head).
// ---------------------------------------------------------------------------
__global__ void norm_rope_kernel(
    const float* __restrict__ gq0, const float* __restrict__ gk0,
    const float* __restrict__ gq1, const float* __restrict__ gk1)
{
    const int s = blockIdx.x;
    const int h = blockIdx.y;
    const int d = threadIdx.x;     // 0..31

    const float* src;
    const float *gq, *gk;
    int pos;
    if (s < S0) {
        pos = s;
        src = g_scratch + OFF_QKV0 + (size_t)s * QKV_N;
        gq = gq0; gk = gk0;
    } else {
        pos = s - S0;
        src = g_scratch + OFF_QKV1 + (size_t)pos * QKV_N;
        gq = gq1; gk = gk1;
    }

    const int col = h * HD + d;
    float qa = src[col],            qb = src[col + 32];
    float ka = src[DIM + col],      kb = src[DIM + col + 32];
    float va = src[2 * DIM + col],  vb = src[2 * DIM + col + 32];

    float ssq = qa * qa + qb * qb;
    float ssk = ka * ka + kb * kb;
    #pragma unroll
    for (int o = 16; o; o >>= 1) {
        ssq += __shfl_xor_sync(0xffffffffu, ssq, o);
        ssk += __shfl_xor_sync(0xffffffffu, ssk, o);
    }
    float rq = rsqrtf(ssq * (1.f / 64.f) + 1e-6f);
    float rk = rsqrtf(ssk * (1.f / 64.f) + 1e-6f);
    qa *= rq * gq[d]; qb *= rq * gq[d + 32];
    ka *= rk * gk[d]; kb *= rk * gk[d + 32];

    float inv = powf(10000.f, -(float)(2 * d) * (1.f / 64.f));
    float f = (float)pos * inv;
    float sn, cs;
    sincosf(f, &sn, &cs);
    float qoa = qa * cs - qb * sn, qob = qb * cs + qa * sn;
    float koa = ka * cs - kb * sn, kob = kb * cs + ka * sn;

    // transposed Q/K: [h][d][s]
    const size_t tb = (size_t)(h * HD) * SEQ + s;
    g_scratch[OFF_Q + tb + (size_t)d * SEQ]        = qoa;
    g_scratch[OFF_Q + tb + (size_t)(d + 32) * SEQ] = qob;
    g_scratch[OFF_K + tb + (size_t)d * SEQ]        = koa;
    g_scratch[OFF_K + tb + (size_t)(d + 32) * SEQ] = kob;
    // natural V: [h][s][d]
    const size_t vb_ = ((size_t)h * SEQ + s) * HD;
    g_scratch[OFF_V + vb_ + d]      = va;
    g_scratch[OFF_V + vb_ + d + 32] = vb;
}

// ---------------------------------------------------------------------------
// Flash attention v4: register-blocked + FFMA2 packed.
// Block = (96-row q-tile, head), 128 threads; thread (ty=t>>3, tx=t&7) owns a
// 6x8 microtile (6 q-rows, 8 k-cols / d-cols). Packed accumulators S2/o2
// pair along the j dimension; b-operands come from float4 smem reads
// (2 packs each), a-operands are dup-packed scalars.
// Q,K arrive pre-transposed from gmem -> smem staging is STS.128, no
// transpose conflicts. Ps is transposed [kcol][qrow] with odd stride.
// ---------------------------------------------------------------------------
#define FL_QT   96
#define FL_SQ   100         // Qs row stride (mult of 4 for STS.128)
#define FL_SK   68          // Ks/Vs row stride
#define FL_SP   99          // Ps row stride (odd -> spread banks)
#define FL_QS_OFF 0
#define FL_KS_OFF (64 * FL_SQ)
#define FL_VS_OFF (FL_KS_OFF + 64 * FL_SK)
#define FL_PS_OFF (FL_VS_OFF + 64 * FL_SK)
#define FL_SMEM_FLOATS (FL_PS_OFF + 64 * FL_SP)
#define FL_SMEM_BYTES (FL_SMEM_FLOATS * 4)   // 64*(100+68+68+99)*4 = 85760 B

__global__ void __launch_bounds__(128) flash_kernel()
{
    extern __shared__ float sm[];
    float* Qs = sm + FL_QS_OFF;   // [d][qrow]
    float* Ks = sm + FL_KS_OFF;   // [d][krow]
    float* Vs = sm + FL_VS_OFF;   // [krow][d]
    float* Ps = sm + FL_PS_OFF;   // [kcol][qrow]

    const int qt = blockIdx.x;
    const int h  = blockIdx.y;
    const int t  = threadIdx.x;
    const int tx = t & 7;
    const int ty = t >> 3;

    const float* Q = g_scratch + OFF_Q;   // [h][d][s]
    const float* K = g_scratch + OFF_K;   // [h][d][s]
    const float* V = g_scratch + OFF_V;   // [h][s][d]

    // Load Q tile: 64 d-rows x 96 s-cols (pre-scaled by 1/8). 1536 float4.
    #pragma unroll
    for (int r = 0; r < 12; r++) {
        int i = r * 128 + t;
        int d = i / 24, c = i - d * 24;
        float4 v = *(const float4*)(Q + (size_t)(h * HD + d) * SEQ
                                      + qt * FL_QT + c * 4);
        v.x *= 0.125f; v.y *= 0.125f; v.z *= 0.125f; v.w *= 0.125f;
        *(float4*)(Qs + d * FL_SQ + c * 4) = v;
    }

    ull o2[6][4];
    #pragma unroll
    for (int i = 0; i < 6; i++)
        #pragma unroll
        for (int j = 0; j < 4; j++) o2[i][j] = 0ull;
    float m[6], l[6];
    #pragma unroll
    for (int i = 0; i < 6; i++) { m[i] = -1e30f; l[i] = 0.f; }

    for (int kt = 0; kt < SEQ; kt += 64) {
        __syncthreads();   // Qs ready (1st iter) / prev PV done with Ks,Vs,Ps

        // K tile: 64 d-rows x 64 krow (transposed source -> coalesced)
        // V tile: 64 krow x 64 d (natural)
        #pragma unroll
        for (int r = 0; r < 8; r++) {
            int i = r * 128 + t;
            int a = i >> 4, c = i & 15;
            float4 kv = *(const float4*)(K + (size_t)(h * HD + a) * SEQ
                                           + kt + c * 4);
            *(float4*)(Ks + a * FL_SK + c * 4) = kv;
            float4 vv = *(const float4*)(V + ((size_t)h * SEQ + kt + a) * HD
                                           + c * 4);
            *(float4*)(Vs + a * FL_SK + c * 4) = vv;
        }
        __syncthreads();

        // ---- QK^T (packed): S2[i][jp] accumulates (s[2jp], s[2jp+1]) ----
        ull S2[6][4];
        #pragma unroll
        for (int i = 0; i < 6; i++)
            #pragma unroll
            for (int j = 0; j < 4; j++) S2[i][j] = 0ull;

        #pragma unroll 4
        for (int d = 0; d < 64; d++) {
            const float* qd = Qs + d * FL_SQ + ty * 6;
            float a0 = qd[0], a1 = qd[1], a2_ = qd[2],
                  a3 = qd[3], a4 = qd[4], a5 = qd[5];
            float4 b0 = *(const float4*)(Ks + d * FL_SK + tx * 8);
            float4 b1 = *(const float4*)(Ks + d * FL_SK + tx * 8 + 4);
            ull bb0 = pk2(b0.x, b0.y), bb1 = pk2(b0.z, b0.w);
            ull bb2 = pk2(b1.x, b1.y), bb3 = pk2(b1.z, b1.w);
            float ar[6] = {a0, a1, a2_, a3, a4, a5};
            #pragma unroll
            for (int i = 0; i < 6; i++) {
                ull aa = pk2(ar[i], ar[i]);
                S2[i][0] = fma2(aa, bb0, S2[i][0]);
                S2[i][1] = fma2(aa, bb1, S2[i][1]);
                S2[i][2] = fma2(aa, bb2, S2[i][2]);
                S2[i][3] = fma2(aa, bb3, S2[i][3]);
            }
        }

        // ---- Online softmax ----
        #pragma unroll
        for (int i = 0; i < 6; i++) {
            float s[8];
            upk2(s[0], s[1], S2[i][0]);
            upk2(s[2], s[3], S2[i][1]);
            upk2(s[4], s[5], S2[i][2]);
            upk2(s[6], s[7], S2[i][3]);
            float mt = s[0];
            #pragma unroll
            for (int j = 1; j < 8; j++) mt = fmaxf(mt, s[j]);
            mt = fmaxf(mt, __shfl_xor_sync(0xffffffffu, mt, 1));
            mt = fmaxf(mt, __shfl_xor_sync(0xffffffffu, mt, 2));
            mt = fmaxf(mt, __shfl_xor_sync(0xffffffffu, mt, 4));
            float mn = fmaxf(m[i], mt);
            float alpha = __expf(m[i] - mn);
            m[i] = mn;
            l[i] *= alpha;
            ull al = pk2(alpha, alpha);
            #pragma unroll
            for (int j = 0; j < 4; j++) o2[i][j] = mul2(o2[i][j], al);

            float rs = 0.f;
            #pragma unroll
            for (int j = 0; j < 8; j++) {
                s[j] = __expf(s[j] - mn);
                rs += s[j];
            }
            rs += __shfl_xor_sync(0xffffffffu, rs, 1);
            rs += __shfl_xor_sync(0xffffffffu, rs, 2);
            rs += __shfl_xor_sync(0xffffffffu, rs, 4);
            l[i] += rs;

            #pragma unroll
            for (int j = 0; j < 8; j++)
                Ps[(tx * 8 + j) * FL_SP + ty * 6 + i] = s[j];
        }
        __syncthreads();

        // ---- PV (packed): o2[i][jp] += P[i][k] * (v[k][2jp], v[k][2jp+1]) --
        #pragma unroll 4
        for (int k = 0; k < 64; k++) {
            const float* pd = Ps + k * FL_SP + ty * 6;
            float p0 = pd[0], p1 = pd[1], p2 = pd[2],
                  p3 = pd[3], p4 = pd[4], p5 = pd[5];
            float4 v0 = *(const float4*)(Vs + k * FL_SK + tx * 8);
            float4 v1 = *(const float4*)(Vs + k * FL_SK + tx * 8 + 4);
            ull bb0 = pk2(v0.x, v0.y), bb1 = pk2(v0.z, v0.w);
            ull bb2 = pk2(v1.x, v1.y), bb3 = pk2(v1.z, v1.w);
            float pr[6] = {p0, p1, p2, p3, p4, p5};
            #pragma unroll
            for (int i = 0; i < 6; i++) {
                ull aa = pk2(pr[i], pr[i]);
                o2[i][0] = fma2(aa, bb0, o2[i][0]);
                o2[i][1] = fma2(aa, bb1, o2[i][1]);
                o2[i][2] = fma2(aa, bb2, o2[i][2]);
                o2[i][3] = fma2(aa, bb3, o2[i][3]);
            }
        }
    }

    // ---- Epilogue: normalize, write O[s][h*64 + d] ----
    #pragma unroll
    for (int i = 0; i < 6; i++) {
        float li = 1.f / l[i];
        float o[8];
        upk2(o[0], o[1], o2[i][0]);
        upk2(o[2], o[3], o2[i][1]);
        upk2(o[4], o[5], o2[i][2]);
        upk2(o[6], o[7], o2[i][3]);
        float* op = g_scratch + OFF_O
                  + (size_t)(qt * FL_QT + ty * 6 + i) * DIM + h * HD + tx * 8;
        *(float4*)(op)     = make_float4(o[0] * li, o[1] * li, o[2] * li, o[3] * li);
        *(float4*)(op + 4) = make_float4(o[4] * li, o[5] * li, o[6] * li, o[7] * li);
    }
}

// ---------------------------------------------------------------------------
// Launch
// ---------------------------------------------------------------------------
extern "C" void kernel_launch(void* const* d_in, const int* in_sizes, int n_in,
                              void* d_out, int out_size)
{
    const float* x0     = (const float*)d_in[0];
    const float* x1     = (const float*)d_in[1];
    const float* w_qkv0 = (const float*)d_in[2];
    const float* w_qkv1 = (const float*)d_in[3];
    const float* w_out0 = (const float*)d_in[4];
    const float* w_out1 = (const float*)d_in[5];
    const float* gq0    = (const float*)d_in[6];
    const float* gk0    = (const float*)d_in[7];
    const float* gq1    = (const float*)d_in[8];
    const float* gk1    = (const float*)d_in[9];
    float* out = (float*)d_out;

    float* scratch = nullptr;
    cudaGetSymbolAddress((void**)&scratch, g_scratch);

    static bool attr_set = false;
    if (!attr_set) {
        cudaFuncSetAttribute(flash_kernel,
                             cudaFuncAttributeMaxDynamicSharedMemorySize,
                             FL_SMEM_BYTES);
        attr_set = true;
    }

    // 1) QKV projections
    sgemm128<<<dim3(QKV_N / 128, S0 / 128), 256>>>(x0, w_qkv0, scratch + OFF_QKV0, QKV_N, DIM);
    sgemm128<<<dim3(QKV_N / 128, S1 / 128), 256>>>(x1, w_qkv1, scratch + OFF_QKV1, QKV_N, DIM);

    // 2) RMSNorm + RoPE -> Q_t/K_t [h][d][s], V [h][s][d]
    norm_rope_kernel<<<dim3(SEQ, NH), 32>>>(gq0, gk0, gq1, gk1);

    // 3) Flash attention -> O[SEQ, H*D]
    flash_kernel<<<dim3(SEQ / FL_QT, NH), 128, FL_SMEM_BYTES>>>();

    // 4) Output projections
    sgemm128<<<dim3(DIM / 128, S0 / 128), 256>>>(scratch + OFF_O, w_out0, out, DIM, DIM);
    sgemm128<<<dim3(DIM / 128, S1 / 128), 256>>>(scratch + OFF_O + (size_t)S0 * DIM,
                                                 w_out1, out + (size_t)S0 * DIM, DIM, DIM);
}